// round 12
// baseline (speedup 1.0000x reference)
#include <cuda_runtime.h>
#include <cstdint>
#include <math.h>

#define NTOK 8192
#define NE   16384
#define CDIM 256
#define HW   1024
#define ZQ_ELEMS (NTOK*CDIM)
#define EPSF 1e-6f

#define NSPLIT2 2
#define MTILE 128
#define NTILE 128
#define NT_PER_CTA ((NE/NSPLIT2)/NTILE)   // 64 tiles
#define DTHREADS 256                       // 8 warps: 2(M) x 4(N), warp tile 64x32

// dist smem (int8 planes): row stride 272 = 256 + 16 pad (≡16 mod 128 -> CF ldsm)
#define BROWQ 272u
#define AROWQ 272u
#define OFF_BQ(buf) ((unsigned)(buf)*34816u)    // 128*272 per buf
#define OFF_E2  69632u                          // 2 x 512B
#define OFF_SE2 70656u                          // 2 x 512B
#define OFF_ZS  71680u                          // 512B (128 token scales)
#define OFF_AQ  72192u                          // 128*272
#define SMEM_DYN_D 107008

// zquant smem: 64 tokens x 257 floats + 64 scales
#define ZQ_SM_SC 65792u
#define SMEM_ZQ (65792 + 256)

// rotate smem
#define R_SM_ET 32992u
#define R_SM_SC (2u*32992u)
#define SMEM_ROT (2*32992 + 1024 + 256)

// ---------------- device scratch (static, allocation-free) ----------------
__device__ float g_emb[NE * CDIM];           // fp32 emb = cb @ W^T (exact)
__device__ float g_e2[NE];                   // |emb_j|^2 (exact)
__device__ float g_se2[NE];                  // 2 * per-code quant scale
__device__ float g_zscale[NTOK];             // per-token quant scale
__device__ signed char g_emb_q[NE * CDIM];   // int8 emb plane
__device__ signed char g_z_q[NTOK * CDIM];   // int8 z plane
__device__ unsigned long long g_cand[NTOK * 8];  // best-4 per (tok, split)

// ---------------- helpers --------------------------------------------------
__device__ __forceinline__ uint32_t smem_u32(const void* p) {
    uint32_t a;
    asm("{ .reg .u64 t; cvta.to.shared.u64 t, %1; cvt.u32.u64 %0, t; }"
        : "=r"(a) : "l"(p));
    return a;
}
__device__ __forceinline__ void cp16(uint32_t dst, const void* src) {
    asm volatile("cp.async.cg.shared.global [%0], [%1], 16;" :: "r"(dst), "l"(src));
}
__device__ __forceinline__ void cp_commit() { asm volatile("cp.async.commit_group;"); }
__device__ __forceinline__ void cp_wait1()  { asm volatile("cp.async.wait_group 1;"); }
#define LDSM4(r0,r1,r2,r3,addr) \
    asm volatile("ldmatrix.sync.aligned.m8n8.x4.shared.b16 {%0,%1,%2,%3}, [%4];" \
        : "=r"(r0), "=r"(r1), "=r"(r2), "=r"(r3) : "r"(addr))
// s8 x s8 -> s32 accumulate, m16n8k32
__device__ __forceinline__ void mma16832q(int* c, const uint32_t* a,
                                          uint32_t b0, uint32_t b1) {
    asm volatile(
        "mma.sync.aligned.m16n8k32.row.col.s32.s8.s8.s32 "
        "{%0,%1,%2,%3}, {%4,%5,%6,%7}, {%8,%9}, {%0,%1,%2,%3};"
        : "+r"(c[0]), "+r"(c[1]), "+r"(c[2]), "+r"(c[3])
        : "r"(a[0]), "r"(a[1]), "r"(a[2]), "r"(a[3]), "r"(b0), "r"(b1));
}
__device__ __forceinline__ unsigned int fkey(float f) {
    unsigned int u = __float_as_uint(f);
    return (u & 0x80000000u) ? ~u : (u | 0x80000000u);
}
__device__ __forceinline__ int q8i(float x, float inv) {
    int v = __float2int_rn(x * inv);
    return v < -127 ? -127 : (v > 127 ? 127 : v);
}
__device__ __forceinline__ uint32_t pack4(int a, int b, int c, int d) {
    return (uint32_t)(a & 255) | ((uint32_t)(b & 255) << 8) |
           ((uint32_t)(c & 255) << 16) | ((uint32_t)(d & 255) << 24);
}
__device__ __forceinline__ void ins2(unsigned long long* b, unsigned long long k) {
    if (k < b[1]) {
        if (k < b[0]) { b[1] = b[0]; b[0] = k; } else b[1] = k;
    }
}
__device__ __forceinline__ void ins4(unsigned long long* b, unsigned long long k) {
    if (k < b[3]) {
        if (k < b[2]) {
            b[3] = b[2];
            if (k < b[1]) {
                b[2] = b[1];
                if (k < b[0]) { b[1] = b[0]; b[0] = k; } else b[1] = k;
            } else b[2] = k;
        } else b[3] = k;
    }
}

// ---------------------------------------------------------------------------
// z quant: fp32 z -> int8 plane (token-major) + per-token scale.
// Block = 64 tokens x all 256 channels.
// ---------------------------------------------------------------------------
__global__ __launch_bounds__(256) void zquant_kernel(const float* __restrict__ z) {
    extern __shared__ char qsm[];
    float (*st)[257] = (float(*)[257])qsm;            // [64][257]
    float* ssc = (float*)(qsm + ZQ_SM_SC);            // [64] inv scales
    const int tid = threadIdx.x;
    const int t0 = blockIdx.x * 64;
    const int bb = t0 >> 10;
    const int hw0 = t0 & (HW - 1);
    const float* zb = z + (size_t)bb * CDIM * HW + hw0;

    #pragma unroll 4
    for (int r = 0; r < 64; r++) {
        const int id = tid + 256 * r;
        const int ch = id >> 6, tt = id & 63;
        st[tt][ch] = zb[(size_t)ch * HW + tt];
    }
    __syncthreads();

    // 4 threads per token compute max|z|
    {
        const int tok = tid >> 2, g = tid & 3;
        float m = 0.0f;
        #pragma unroll
        for (int i = 0; i < 64; i++)
            m = fmaxf(m, fabsf(st[tok][g * 64 + i]));
        m = fmaxf(m, __shfl_xor_sync(0xFFFFFFFFu, m, 1));
        m = fmaxf(m, __shfl_xor_sync(0xFFFFFFFFu, m, 2));
        m = fmaxf(m, 1e-3f);
        if (g == 0) {
            g_zscale[t0 + tok] = m / 127.0f;
            ssc[tok] = 127.0f / m;
        }
    }
    __syncthreads();

    #pragma unroll
    for (int r = 0; r < 16; r++) {
        const int id = tid + 256 * r;
        const int tok = id >> 6, w = id & 63;
        const float inv = ssc[tok];
        const uint32_t p = pack4(q8i(st[tok][4*w],   inv), q8i(st[tok][4*w+1], inv),
                                 q8i(st[tok][4*w+2], inv), q8i(st[tok][4*w+3], inv));
        ((uint32_t*)g_z_q)[(size_t)(t0 + tok) * 64 + w] = p;
    }
}

// ---------------------------------------------------------------------------
// emb = codebook @ W^T fp32 (exact vs reference)
// ---------------------------------------------------------------------------
__global__ __launch_bounds__(256) void emb_kernel(const float* __restrict__ cb,
                                                  const float* __restrict__ W) {
    __shared__ float As[16][68];
    __shared__ float Bs[16][68];
    const int t  = threadIdx.x;
    const int tx = t & 15, ty = t >> 4;
    const int m0 = blockIdx.y * 64;
    const int n0 = blockIdx.x * 64;

    float acc[4][4] = {};
    for (int k0 = 0; k0 < CDIM; k0 += 16) {
        __syncthreads();
        const int kk = t & 15, mm = t >> 4;
        #pragma unroll
        for (int r = 0; r < 4; r++) {
            As[kk][mm + 16*r] = cb[(m0 + mm + 16*r) * CDIM + k0 + kk];
            Bs[kk][mm + 16*r] = W [(n0 + mm + 16*r) * CDIM + k0 + kk];
        }
        __syncthreads();
        #pragma unroll
        for (int k = 0; k < 16; k++) {
            float4 a = *(const float4*)&As[k][ty * 4];
            float4 b = *(const float4*)&Bs[k][tx * 4];
            float av[4] = {a.x, a.y, a.z, a.w};
            float bv[4] = {b.x, b.y, b.z, b.w};
            #pragma unroll
            for (int i = 0; i < 4; i++)
                #pragma unroll
                for (int j = 0; j < 4; j++)
                    acc[i][j] = fmaf(av[i], bv[j], acc[i][j]);
        }
    }
    #pragma unroll
    for (int i = 0; i < 4; i++) {
        const int code = m0 + ty * 4 + i;
        float4 v = make_float4(acc[i][0], acc[i][1], acc[i][2], acc[i][3]);
        *(float4*)&g_emb[code * CDIM + n0 + tx * 4] = v;
    }
}

// deterministic e2 + per-code scale + int8 quant + loss-slot init
__global__ __launch_bounds__(256) void e2q_kernel(float* out, int out_size) {
    const int code = blockIdx.x * 8 + (threadIdx.x >> 5);
    const int lane = threadIdx.x & 31;
    const float* row = g_emb + (size_t)code * CDIM;
    float v[8];
    float s = 0.0f, m = 0.0f;
    #pragma unroll
    for (int i = 0; i < 8; i++) {
        v[i] = row[lane + 32 * i];
        s = fmaf(v[i], v[i], s);
        m = fmaxf(m, fabsf(v[i]));
    }
    #pragma unroll
    for (int off = 16; off > 0; off >>= 1) {
        s += __shfl_xor_sync(0xFFFFFFFFu, s, off);
        m = fmaxf(m, __shfl_xor_sync(0xFFFFFFFFu, m, off));
    }
    m = fmaxf(m, 1e-6f);
    const float inv = 127.0f / m;
    if (lane == 0) {
        g_e2[code] = s;
        g_se2[code] = 2.0f * (m / 127.0f);
    }
    #pragma unroll
    for (int i = 0; i < 8; i++)
        g_emb_q[(size_t)code * CDIM + lane + 32 * i] = (signed char)q8i(v[i], inv);
    if (blockIdx.x == 0 && threadIdx.x == 0 && out_size > ZQ_ELEMS) out[ZQ_ELEMS] = 0.0f;
}

// ---------------------------------------------------------------------------
// Distance GEMM: int8 IMMA m16n8k32, CTA 128x128, 8 warps (2M x 4N, 64x32).
// score = e2[c] - sz_t * se2[c] * dot ; pair-min -> best-2/row -> best-4/split.
// ---------------------------------------------------------------------------
__global__ __launch_bounds__(DTHREADS, 1) void dist_kernel(float* dummy) {
    extern __shared__ char smem[];
    const uint32_t sb = smem_u32(smem);
    const int tid  = threadIdx.x;
    const int lane = tid & 31, wid = tid >> 5;
    const int gid  = lane >> 2, tig = lane & 3;
    const int wm = wid & 1, wn = wid >> 1;
    const int m_base = wm * 64, n_base = wn * 32;
    const int m0 = blockIdx.y * MTILE;
    const int nbase = blockIdx.x * (NE / NSPLIT2);

    // staging offsets: 16 chunks of 16B per 256B row
    const unsigned st_off = (unsigned)(tid >> 4) * AROWQ + (unsigned)(tid & 15) * 16u;
    const size_t   src_off = (size_t)(tid >> 4) * 256 + (size_t)(tid & 15) * 16;

    // ---- prologue: stage A, B tile0, e2/se2 tile0, zscale; commit group 0 --
    {
        const signed char* zq = g_z_q + (size_t)m0 * CDIM + src_off;
        const signed char* bq0 = g_emb_q + (size_t)nbase * CDIM + src_off;
        #pragma unroll
        for (int r = 0; r < 8; r++) {
            cp16(sb + OFF_AQ + st_off + (unsigned)r * (16u * AROWQ), zq + (size_t)r * 4096);
            cp16(sb + OFF_BQ(0) + st_off + (unsigned)r * (16u * AROWQ), bq0 + (size_t)r * 4096);
        }
        if (tid < 32) {
            cp16(sb + OFF_E2 + (unsigned)tid * 16u, g_e2 + nbase + tid * 4);
            cp16(sb + OFF_SE2 + (unsigned)tid * 16u, g_se2 + nbase + tid * 4);
            cp16(sb + OFF_ZS + (unsigned)tid * 16u, g_zscale + m0 + tid * 4);
        }
        cp_commit();
    }

    // lane-invariant ldmatrix base offsets (16B col-half units)
    const uint32_t aoffA = (uint32_t)((m_base + ((lane >> 3) & 1) * 8 + (lane & 7)) * AROWQ
                                      + (lane >> 4) * 16);
    const uint32_t aAq = sb + OFF_AQ + aoffA;
    const uint32_t boffB = (uint32_t)((n_base + (lane >> 4) * 8 + (lane & 7)) * BROWQ
                                      + ((lane >> 3) & 1) * 16);

    unsigned long long bL[8][2];
    #pragma unroll
    for (int i = 0; i < 8; i++) { bL[i][0] = ~0ULL; bL[i][1] = ~0ULL; }
    float szr[8];

    const signed char* bsrc = g_emb_q + (size_t)(nbase + NTILE) * CDIM + src_off;
    const float* e2src = g_e2 + nbase + NTILE + (tid < 32 ? tid * 4 : 0);
    const float* se2src = g_se2 + nbase + NTILE + (tid < 32 ? tid * 4 : 0);

    for (int nt = 0; nt < NT_PER_CTA; nt++) {
        const int buf = nt & 1;
        if (nt + 1 < NT_PER_CTA) {
            const uint32_t dstb = sb + OFF_BQ(buf ^ 1) + st_off;
            #pragma unroll
            for (int r = 0; r < 8; r++)
                cp16(dstb + (unsigned)r * (16u * BROWQ), bsrc + (size_t)r * 4096);
            if (tid < 32) {
                cp16(sb + OFF_E2 + (unsigned)(buf ^ 1) * 512u + (unsigned)tid * 16u, e2src);
                cp16(sb + OFF_SE2 + (unsigned)(buf ^ 1) * 512u + (unsigned)tid * 16u, se2src);
            }
        }
        cp_commit();
        cp_wait1();
        __syncthreads();
        bsrc += (size_t)NTILE * CDIM;
        e2src += NTILE;
        se2src += NTILE;

        if (nt == 0) {
            const float* zsp = (const float*)(smem + OFF_ZS);
            #pragma unroll
            for (int l = 0; l < 8; l++)
                szr[l] = zsp[m_base + (l >> 1) * 16 + gid + (l & 1) * 8];
        }

        // ---- mainloop: 8 k-steps (k32 each), 6 LDSM + 16 IMMA per step ----
        int acc[4][4][4] = {};
        const uint32_t Bq = sb + OFF_BQ(buf) + boffB;
        #pragma unroll
        for (int s = 0; s < 8; s++) {
            uint32_t ah[4][4], bh[2][4];
            const uint32_t ko = (uint32_t)(s * 32);
            #pragma unroll
            for (int ma = 0; ma < 4; ma++)
                LDSM4(ah[ma][0], ah[ma][1], ah[ma][2], ah[ma][3],
                      aAq + (uint32_t)(ma * 16) * AROWQ + ko);
            #pragma unroll
            for (int nb = 0; nb < 2; nb++)
                LDSM4(bh[nb][0], bh[nb][1], bh[nb][2], bh[nb][3],
                      Bq + (uint32_t)(nb * 16) * BROWQ + ko);
            #pragma unroll
            for (int nb = 0; nb < 2; nb++)
                #pragma unroll
                for (int h = 0; h < 2; h++)
                    #pragma unroll
                    for (int ma = 0; ma < 4; ma++)
                        mma16832q(acc[ma][nb*2+h], ah[ma], bh[nb][2*h], bh[nb][2*h+1]);
        }

        // ---- epilogue: dequant scores, pair-min, best-2 insert ----
        {
            const float* e2p = (const float*)(smem + OFF_E2 + (size_t)buf * 512);
            const float* sep = (const float*)(smem + OFF_SE2 + (size_t)buf * 512);
            const int n0 = nbase + nt * NTILE;
            #pragma unroll
            for (int na = 0; na < 4; na++) {
                const int cc = n_base + na * 8 + tig * 2;
                const float e2a = e2p[cc], e2b = e2p[cc + 1];
                const float sea = sep[cc], seb = sep[cc + 1];
                const int c0 = n0 + cc;
                #pragma unroll
                for (int ma = 0; ma < 4; ma++) {
                    {
                        const float sz = szr[ma * 2 + 0];
                        const float s0 = fmaf(-sz, (float)acc[ma][na][0] * sea, e2a);
                        const float s1 = fmaf(-sz, (float)acc[ma][na][1] * seb, e2b);
                        const float sm = fminf(s0, s1);
                        const unsigned cm = (s0 <= s1) ? (unsigned)c0 : (unsigned)(c0 + 1);
                        ins2(bL[ma * 2 + 0], ((unsigned long long)fkey(sm) << 32) | cm);
                    }
                    {
                        const float sz = szr[ma * 2 + 1];
                        const float s0 = fmaf(-sz, (float)acc[ma][na][2] * sea, e2a);
                        const float s1 = fmaf(-sz, (float)acc[ma][na][3] * seb, e2b);
                        const float sm = fminf(s0, s1);
                        const unsigned cm = (s0 <= s1) ? (unsigned)c0 : (unsigned)(c0 + 1);
                        ins2(bL[ma * 2 + 1], ((unsigned long long)fkey(sm) << 32) | cm);
                    }
                }
            }
        }
        __syncthreads();
    }

    // ---- merge over tig lanes (same token rows) ----
    #pragma unroll
    for (int off = 1; off <= 2; off <<= 1) {
        #pragma unroll
        for (int l = 0; l < 8; l++) {
            #pragma unroll
            for (int e = 0; e < 2; e++) {
                const unsigned long long ok = __shfl_xor_sync(0xFFFFFFFFu, bL[l][e], off);
                ins2(bL[l], ok);
            }
        }
    }
    __syncthreads();
    unsigned long long* red = (unsigned long long*)smem;  // 128 rows x 4 wn x 2 keys
    if (tig == 0) {
        #pragma unroll
        for (int l = 0; l < 8; l++) {
            const int row = m_base + (l >> 1) * 16 + gid + (l & 1) * 8;
            red[(row * 4 + wn) * 2 + 0] = bL[l][0];
            red[(row * 4 + wn) * 2 + 1] = bL[l][1];
        }
    }
    __syncthreads();
    if (tid < 128) {
        unsigned long long b[4] = {~0ULL, ~0ULL, ~0ULL, ~0ULL};
        #pragma unroll
        for (int w = 0; w < 4; w++) {
            ins4(b, red[(tid * 4 + w) * 2 + 0]);
            ins4(b, red[(tid * 4 + w) * 2 + 1]);
        }
        #pragma unroll
        for (int e = 0; e < 4; e++)
            g_cand[(size_t)(m0 + tid) * 8 + blockIdx.x * 4 + e] = b[e];
    }
}

// ---------------------------------------------------------------------------
// Refine (exact fp32, 8 candidates) + rotation, coalesced.
// ---------------------------------------------------------------------------
__global__ __launch_bounds__(256) void rotate_kernel(const float* __restrict__ z,
                                                     float* __restrict__ out,
                                                     int out_size) {
    extern __shared__ char rsm[];
    float (*zt)[257] = (float(*)[257])rsm;
    float (*et)[257] = (float(*)[257])(rsm + R_SM_ET);
    float (*ssc)[8]  = (float(*)[8]) (rsm + R_SM_SC);
    const int tid = threadIdx.x, lane = tid & 31, wid = tid >> 5;
    const int t0 = blockIdx.x * 32;
    const int bb = t0 >> 10, hw0 = t0 & (HW - 1);
    const float* zb = z + (size_t)bb * CDIM * HW + hw0;

    #pragma unroll
    for (int i = 0; i < 32; i++) {
        const int c = wid * 32 + i;
        zt[lane][c] = zb[(size_t)c * HW + lane];
    }
    __syncthreads();

    for (int q = 0; q < 4; q++) {
        const int tt = wid * 4 + q;
        const int gtok = t0 + tt;
        int cand[8];
        #pragma unroll
        for (int i = 0; i < 8; i++)
            cand[i] = (int)(g_cand[(size_t)gtok * 8 + i] & 0xFFFFFFFFULL);
        float p[8] = {0.f,0.f,0.f,0.f,0.f,0.f,0.f,0.f};
        #pragma unroll
        for (int j = 0; j < 8; j++) {
            const int c = lane + 32 * j;
            const float zv = zt[tt][c];
            #pragma unroll
            for (int i = 0; i < 8; i++)
                p[i] = fmaf(zv, __ldg(&g_emb[(size_t)cand[i] * CDIM + c]), p[i]);
        }
        #pragma unroll
        for (int i = 0; i < 8; i++)
            #pragma unroll
            for (int off = 16; off > 0; off >>= 1)
                p[i] += __shfl_xor_sync(0xFFFFFFFFu, p[i], off);
        unsigned long long bk = ~0ULL;
        float zebest = 0.0f;
        #pragma unroll
        for (int i = 0; i < 8; i++) {
            const float s = fmaf(-2.0f, p[i], __ldg(&g_e2[cand[i]]));
            const unsigned long long key =
                ((unsigned long long)fkey(s) << 32) | (unsigned)cand[i];
            if (key < bk) { bk = key; zebest = p[i]; }
        }
        const int idx = (int)(bk & 0xFFFFFFFFULL);

        float zz = 0.0f;
        #pragma unroll
        for (int j = 0; j < 8; j++) {
            const int c = lane + 32 * j;
            const float ev = __ldg(&g_emb[(size_t)idx * CDIM + c]);
            et[tt][c] = ev;
            const float zv = zt[tt][c];
            zz = fmaf(zv, zv, zz);
        }
        #pragma unroll
        for (int off = 16; off > 0; off >>= 1)
            zz += __shfl_xor_sync(0xFFFFFFFFu, zz, off);
        const float ZZ = zz, ZE = zebest, EE = __ldg(&g_e2[idx]);
        if (lane == 0) {
            const float ns = sqrtf(ZZ), ntg = sqrtf(EE);
            const float rdns = 1.0f / (ns + EPSF), rdnt = 1.0f / (ntg + EPSF);
            const float uq2 = ZZ*rdns*rdns + 2.0f*ZE*rdns*rdnt + EE*rdnt*rdnt;
            const float rdnw = 1.0f / (sqrtf(uq2) + EPSF);
            ssc[tt][0] = rdns;
            ssc[tt][1] = rdnt;
            ssc[tt][2] = rdnw;
            ssc[tt][3] = (ZZ * rdns + ZE * rdnt) * rdnw;
            ssc[tt][4] = ZZ * rdns;
            ssc[tt][5] = ntg * rdns;
            if (out_size > ZQ_ELEMS) {
                const float sq = ZZ - 2.0f * ZE + EE;
                atomicAdd(&out[ZQ_ELEMS], 1.25f * sq / (float)ZQ_ELEMS);
            }
            if (out_size >= ZQ_ELEMS + 1 + NTOK)
                out[ZQ_ELEMS + 1 + gtok] = (float)idx;
        }
    }
    __syncthreads();

    const float rdns = ssc[lane][0], rdnt = ssc[lane][1], rdnw = ssc[lane][2];
    const float sw = ssc[lane][3], su = ssc[lane][4], scale = ssc[lane][5];
    float* ob = out + (size_t)bb * CDIM * HW + hw0;
    #pragma unroll
    for (int i = 0; i < 32; i++) {
        const int c = wid * 32 + i;
        const float zc = zt[lane][c];
        const float ec = et[lane][c];
        const float q_ch = ec * rdnt;
        const float w_ch = (zc * rdns + q_ch) * rdnw;
        const float rot = zc - 2.0f * sw * w_ch + 2.0f * su * q_ch;
        ob[(size_t)c * HW + lane] = rot * scale;
    }
}

extern "C" void kernel_launch(void* const* d_in, const int* in_sizes, int n_in,
                              void* d_out, int out_size) {
    const float* z  = (const float*)d_in[0];   // (8,256,32,32)
    const float* cb = (const float*)d_in[1];   // (16384,256)
    const float* W  = (const float*)d_in[2];   // (256,256)
    float* out = (float*)d_out;

    cudaFuncSetAttribute(dist_kernel,
                         cudaFuncAttributeMaxDynamicSharedMemorySize, SMEM_DYN_D);
    cudaFuncSetAttribute(rotate_kernel,
                         cudaFuncAttributeMaxDynamicSharedMemorySize, SMEM_ROT);
    cudaFuncSetAttribute(zquant_kernel,
                         cudaFuncAttributeMaxDynamicSharedMemorySize, SMEM_ZQ);

    zquant_kernel<<<NTOK / 64, 256, SMEM_ZQ>>>(z);
    emb_kernel<<<dim3(4, NE / 64), 256>>>(cb, W);
    e2q_kernel<<<NE / 8, 256>>>(out, out_size);
    dist_kernel<<<dim3(NSPLIT2, NTOK / MTILE), DTHREADS, SMEM_DYN_D>>>(out);
    rotate_kernel<<<NTOK / 32, 256, SMEM_ROT>>>(z, out, out_size);
}

// round 13
// speedup vs baseline: 2.0209x; 2.0209x over previous
#include <cuda_runtime.h>
#include <cuda_fp16.h>
#include <cstdint>
#include <math.h>

#define NTOK 8192
#define NE   16384
#define CDIM 256
#define HW   1024
#define ZQ_ELEMS (NTOK*CDIM)
#define EPSF 1e-6f

#define MTILE 128
#define NTILE 128
#define NSB 16                  // code blocks of 1024 codes
#define NT_PER_ITEM 8           // 8 x 128-code tiles per item
#define NITEMS (64*NSB)         // 64 token tiles x 16 blocks = 1024
#define DGRID 152
#define DTHREADS 256            // 8 warps: 2(M) x 4(N), warp tile 64x32

// dist smem: A plane (full K) + 2 full-K B buffers + e2 double buffer + item slot
#define AROW 528u
#define BROW 528u
#define OFF_B(buf) ((unsigned)(buf)*67584u)     // 128*528 per buf
#define OFF_E2 135168u                          // 2 x 512B
#define OFF_AH 136192u
#define OFF_ITEM 203776u
#define SMEM_DYN_D 203792

// rotate smem
#define R_SM_ET 32992u
#define R_SM_SC (2u*32992u)
#define SMEM_ROT (2*32992 + 1024 + 256)

// ---------------- device scratch (static, allocation-free) ----------------
__device__ float g_emb[NE * CDIM];            // fp32 emb = cb @ W^T (exact)
__device__ float g_e2[NE];                    // |emb_j|^2
__device__ unsigned short g_emb_h[NE * CDIM]; // fp16 plane
__device__ unsigned short g_z_h[NTOK * CDIM]; // fp16 plane
__device__ unsigned long long g_cand[NTOK * 32];  // best-2 per (tok, block)
__device__ unsigned long long g_cand8[NTOK * 8];  // merged best-8 per tok
__device__ int g_ctr;                             // work-steal counter

// ---------------- helpers --------------------------------------------------
__device__ __forceinline__ uint32_t smem_u32(const void* p) {
    uint32_t a;
    asm("{ .reg .u64 t; cvta.to.shared.u64 t, %1; cvt.u32.u64 %0, t; }"
        : "=r"(a) : "l"(p));
    return a;
}
__device__ __forceinline__ void cp16(uint32_t dst, const void* src) {
    asm volatile("cp.async.cg.shared.global [%0], [%1], 16;" :: "r"(dst), "l"(src));
}
__device__ __forceinline__ void cp_commit() { asm volatile("cp.async.commit_group;"); }
__device__ __forceinline__ void cp_wait1()  { asm volatile("cp.async.wait_group 1;"); }
#define LDSM4(r0,r1,r2,r3,addr) \
    asm volatile("ldmatrix.sync.aligned.m8n8.x4.shared.b16 {%0,%1,%2,%3}, [%4];" \
        : "=r"(r0), "=r"(r1), "=r"(r2), "=r"(r3) : "r"(addr))
__device__ __forceinline__ void mma16816h(uint32_t* c, const uint32_t* a,
                                          uint32_t b0, uint32_t b1) {
    asm volatile(
        "mma.sync.aligned.m16n8k16.row.col.f16.f16.f16.f16 "
        "{%0,%1}, {%2,%3,%4,%5}, {%6,%7}, {%0,%1};"
        : "+r"(c[0]), "+r"(c[1])
        : "r"(a[0]), "r"(a[1]), "r"(a[2]), "r"(a[3]), "r"(b0), "r"(b1));
}
__device__ __forceinline__ float2 h2f2(uint32_t v) {
    __half2 h = *reinterpret_cast<__half2*>(&v);
    return __half22float2(h);
}
__device__ __forceinline__ unsigned int fkey(float f) {
    unsigned int u = __float_as_uint(f);
    return (u & 0x80000000u) ? ~u : (u | 0x80000000u);
}
__device__ __forceinline__ unsigned short hfu(float f) {
    return __half_as_ushort(__float2half_rn(f));
}
__device__ __forceinline__ void ins2(unsigned long long* b, unsigned long long k) {
    if (k < b[1]) {
        if (k < b[0]) { b[1] = b[0]; b[0] = k; } else b[1] = k;
    }
}

// ---------------------------------------------------------------------------
// z split: fp32 z -> fp16 plane, token-major rows. Also resets work counter.
// ---------------------------------------------------------------------------
__global__ __launch_bounds__(256) void zsplit_kernel(const float* __restrict__ z) {
    __shared__ float s[64][65];
    const int tid = threadIdx.x;
    if (blockIdx.x == 0 && blockIdx.y == 0 && tid == 0) g_ctr = 0;
    const int t0 = blockIdx.y * 64;
    const int p0 = blockIdx.x * 32;
    const int bb = t0 >> 10;
    const int hw0 = t0 & (HW - 1);
    const float* zb = z + (size_t)bb * CDIM * HW + hw0;

    #pragma unroll
    for (int r = 0; r < 16; r++) {
        const int id = tid + 256 * r;
        const int kk = id >> 6, tt = id & 63;
        s[kk][tt] = zb[(size_t)(2 * p0 + kk) * HW + tt];
    }
    __syncthreads();
    #pragma unroll
    for (int r = 0; r < 8; r++) {
        const int id = tid + 256 * r;
        const int tt = id >> 5, pp = id & 31;
        const float z0 = s[2 * pp][tt], z1 = s[2 * pp + 1][tt];
        ((uint32_t*)g_z_h)[(size_t)(t0 + tt) * 128 + p0 + pp] =
            (uint32_t)hfu(z0) | ((uint32_t)hfu(z1) << 16);
    }
}

// ---------------------------------------------------------------------------
// emb = codebook @ W^T fp32 (exact) + fp16 plane output
// ---------------------------------------------------------------------------
__global__ __launch_bounds__(256) void emb_kernel(const float* __restrict__ cb,
                                                  const float* __restrict__ W) {
    __shared__ float As[16][68];
    __shared__ float Bs[16][68];
    const int t  = threadIdx.x;
    const int tx = t & 15, ty = t >> 4;
    const int m0 = blockIdx.y * 64;
    const int n0 = blockIdx.x * 64;

    float acc[4][4] = {};
    for (int k0 = 0; k0 < CDIM; k0 += 16) {
        __syncthreads();
        const int kk = t & 15, mm = t >> 4;
        #pragma unroll
        for (int r = 0; r < 4; r++) {
            As[kk][mm + 16*r] = cb[(m0 + mm + 16*r) * CDIM + k0 + kk];
            Bs[kk][mm + 16*r] = W [(n0 + mm + 16*r) * CDIM + k0 + kk];
        }
        __syncthreads();
        #pragma unroll
        for (int k = 0; k < 16; k++) {
            float4 a = *(const float4*)&As[k][ty * 4];
            float4 b = *(const float4*)&Bs[k][tx * 4];
            float av[4] = {a.x, a.y, a.z, a.w};
            float bv[4] = {b.x, b.y, b.z, b.w};
            #pragma unroll
            for (int i = 0; i < 4; i++)
                #pragma unroll
                for (int j = 0; j < 4; j++)
                    acc[i][j] = fmaf(av[i], bv[j], acc[i][j]);
        }
    }
    #pragma unroll
    for (int i = 0; i < 4; i++) {
        const int code = m0 + ty * 4 + i;
        float4 v = make_float4(acc[i][0], acc[i][1], acc[i][2], acc[i][3]);
        const int e0 = code * CDIM + n0 + tx * 4;
        *(float4*)&g_emb[e0] = v;
        uint2 hp;
        hp.x = (uint32_t)hfu(v.x) | ((uint32_t)hfu(v.y) << 16);
        hp.y = (uint32_t)hfu(v.z) | ((uint32_t)hfu(v.w) << 16);
        ((uint2*)g_emb_h)[e0 >> 2] = hp;
    }
}

// deterministic e2 + loss-slot init
__global__ __launch_bounds__(256) void e2_kernel(float* out, int out_size) {
    const int code = blockIdx.x * 8 + (threadIdx.x >> 5);
    const int lane = threadIdx.x & 31;
    const float* row = g_emb + (size_t)code * CDIM;
    float s = 0.0f;
    #pragma unroll
    for (int i = 0; i < 8; i++) { float v = row[lane + 32*i]; s = fmaf(v, v, s); }
    #pragma unroll
    for (int off = 16; off > 0; off >>= 1) s += __shfl_xor_sync(0xFFFFFFFFu, s, off);
    if (lane == 0) g_e2[code] = s;
    if (blockIdx.x == 0 && threadIdx.x == 0 && out_size > ZQ_ELEMS) out[ZQ_ELEMS] = 0.0f;
}

// ---------------------------------------------------------------------------
// Distance GEMM: persistent work-stealing. Item = (token tile 128, 1024 codes).
// 8 warps = 2(M) x 4(N), warp tile 64x32, fp16 HMMA. best-2 per (tok, block).
// ---------------------------------------------------------------------------
__global__ __launch_bounds__(DTHREADS, 1) void dist_kernel(float* dummy) {
    extern __shared__ char smem[];
    const uint32_t sb = smem_u32(smem);
    int* s_item = (int*)(smem + OFF_ITEM);
    const int tid  = threadIdx.x;
    const int lane = tid & 31, wid = tid >> 5;
    const int gid  = lane >> 2, tig = lane & 3;
    const int wm = wid & 1, wn = wid >> 1;
    const int m_base = wm * 64, n_base = wn * 32;

    const unsigned st_off = (unsigned)(tid >> 5) * 528u + (unsigned)(tid & 31) * 16u;
    const size_t   src_off = (size_t)(tid >> 5) * 256 + (size_t)(tid & 31) * 8;

    const uint32_t aoffA = (uint32_t)((m_base + ((lane >> 3) & 1) * 8 + (lane & 7)) * AROW
                                      + ((lane >> 4) * 8) * 2);
    const uint32_t aAh = sb + OFF_AH + aoffA;
    const uint32_t boffB = (uint32_t)((n_base + (lane >> 4) * 8 + (lane & 7)) * BROW
                                      + (((lane >> 3) & 1) * 8) * 2);

    int last_tt = -1;

    for (;;) {
        if (tid == 0) *s_item = atomicAdd(&g_ctr, 1);
        __syncthreads();
        const int item = *s_item;
        if (item >= NITEMS) break;
        const int tt = item >> 4, sbk = item & (NSB - 1);
        const int m0 = tt * MTILE;
        const int nbase = sbk * 1024;

        // ---- prologue: A (only if token tile changed), B tile 0, e2 tile 0 --
        if (tt != last_tt) {
            const unsigned short* zh = g_z_h + (size_t)m0 * CDIM + src_off;
            #pragma unroll
            for (int r = 0; r < 16; r++)
                cp16(sb + OFF_AH + st_off + (unsigned)r * (8u * 528u),
                     zh + (size_t)r * 2048);
            last_tt = tt;
        }
        {
            const unsigned short* bh0 = g_emb_h + (size_t)nbase * CDIM + src_off;
            #pragma unroll
            for (int r = 0; r < 16; r++)
                cp16(sb + OFF_B(0) + st_off + (unsigned)r * (8u * 528u),
                     bh0 + (size_t)r * 2048);
            if (tid < 32) cp16(sb + OFF_E2 + (unsigned)tid * 16u, g_e2 + nbase + tid * 4);
            cp_commit();
        }

        unsigned long long bL[8][2];
        #pragma unroll
        for (int i = 0; i < 8; i++) { bL[i][0] = ~0ULL; bL[i][1] = ~0ULL; }

        const unsigned short* bsrc = g_emb_h + (size_t)(nbase + NTILE) * CDIM + src_off;
        const float* e2src = g_e2 + nbase + NTILE + (tid < 32 ? tid * 4 : 0);

        for (int nt = 0; nt < NT_PER_ITEM; nt++) {
            const int buf = nt & 1;
            if (nt + 1 < NT_PER_ITEM) {
                const uint32_t dstb = sb + OFF_B(buf ^ 1) + st_off;
                #pragma unroll
                for (int r = 0; r < 16; r++)
                    cp16(dstb + (unsigned)r * (8u * 528u), bsrc + (size_t)r * 2048);
                if (tid < 32)
                    cp16(sb + OFF_E2 + (unsigned)(buf ^ 1) * 512u + (unsigned)tid * 16u,
                         e2src);
            }
            cp_commit();
            cp_wait1();
            __syncthreads();
            bsrc += (size_t)NTILE * CDIM;
            e2src += NTILE;

            // ---- mainloop: 16 k-steps, f16-accum HMMA ----
            uint32_t acc[4][4][2] = {};
            const uint32_t Bh = sb + OFF_B(buf) + boffB;
            #pragma unroll
            for (int s = 0; s < 16; s++) {
                uint32_t ah[4][4], bh[2][4];
                const uint32_t ko = (uint32_t)(s * 32);
                #pragma unroll
                for (int ma = 0; ma < 4; ma++)
                    LDSM4(ah[ma][0], ah[ma][1], ah[ma][2], ah[ma][3],
                          aAh + (uint32_t)(ma * 16) * AROW + ko);
                #pragma unroll
                for (int nb = 0; nb < 2; nb++)
                    LDSM4(bh[nb][0], bh[nb][1], bh[nb][2], bh[nb][3],
                          Bh + (uint32_t)(nb * 16) * BROW + ko);
                #pragma unroll
                for (int nb = 0; nb < 2; nb++)
                    #pragma unroll
                    for (int h = 0; h < 2; h++)
                        #pragma unroll
                        for (int ma = 0; ma < 4; ma++)
                            mma16816h(acc[ma][nb*2+h], ah[ma], bh[nb][2*h], bh[nb][2*h+1]);
            }

            // ---- epilogue: scores, pair-min, best-2 insert ----
            {
                const float* e2p = (const float*)(smem + OFF_E2 + (size_t)buf * 512);
                const int n0 = nbase + nt * NTILE;
                #pragma unroll
                for (int na = 0; na < 4; na++) {
                    const int cc = n_base + na * 8 + tig * 2;
                    const float e2a = e2p[cc], e2b = e2p[cc + 1];
                    const int c0 = n0 + cc;
                    #pragma unroll
                    for (int ma = 0; ma < 4; ma++) {
                        {
                            const float2 v = h2f2(acc[ma][na][0]);
                            const float s0 = fmaf(-2.0f, v.x, e2a);
                            const float s1 = fmaf(-2.0f, v.y, e2b);
                            const float sm = fminf(s0, s1);
                            const unsigned cm = (s0 <= s1) ? (unsigned)c0 : (unsigned)(c0 + 1);
                            ins2(bL[ma * 2 + 0], ((unsigned long long)fkey(sm) << 32) | cm);
                        }
                        {
                            const float2 v = h2f2(acc[ma][na][1]);
                            const float s0 = fmaf(-2.0f, v.x, e2a);
                            const float s1 = fmaf(-2.0f, v.y, e2b);
                            const float sm = fminf(s0, s1);
                            const unsigned cm = (s0 <= s1) ? (unsigned)c0 : (unsigned)(c0 + 1);
                            ins2(bL[ma * 2 + 1], ((unsigned long long)fkey(sm) << 32) | cm);
                        }
                    }
                }
            }
            __syncthreads();
        }

        // ---- per-item merge: tig lanes -> smem -> best-2 per token row ----
        #pragma unroll
        for (int off = 1; off <= 2; off <<= 1) {
            #pragma unroll
            for (int l = 0; l < 8; l++) {
                #pragma unroll
                for (int e = 0; e < 2; e++) {
                    const unsigned long long ok = __shfl_xor_sync(0xFFFFFFFFu, bL[l][e], off);
                    ins2(bL[l], ok);
                }
            }
        }
        __syncthreads();
        unsigned long long* red = (unsigned long long*)smem;  // 128 x 4 wn x 2 (8 KB)
        if (tig == 0) {
            #pragma unroll
            for (int l = 0; l < 8; l++) {
                const int row = m_base + (l >> 1) * 16 + gid + (l & 1) * 8;
                red[(row * 4 + wn) * 2 + 0] = bL[l][0];
                red[(row * 4 + wn) * 2 + 1] = bL[l][1];
            }
        }
        __syncthreads();
        if (tid < 128) {
            unsigned long long b[2] = {~0ULL, ~0ULL};
            #pragma unroll
            for (int w = 0; w < 4; w++) {
                ins2(b, red[(tid * 4 + w) * 2 + 0]);
                ins2(b, red[(tid * 4 + w) * 2 + 1]);
            }
            const size_t slot = ((size_t)(m0 + tid) * NSB + sbk) * 2;
            g_cand[slot + 0] = b[0];
            g_cand[slot + 1] = b[1];
        }
        __syncthreads();   // red reads done before next item's B tile 0 staging
    }
}

// ---------------------------------------------------------------------------
// merge 32 keys per token -> best-8
// ---------------------------------------------------------------------------
__global__ __launch_bounds__(256) void merge8_kernel() {
    const int tok = blockIdx.x * 256 + threadIdx.x;
    unsigned long long b[8];
    #pragma unroll
    for (int i = 0; i < 8; i++) b[i] = ~0ULL;
    const unsigned long long* src = g_cand + (size_t)tok * 32;
    for (int j = 0; j < 32; j++) {
        const unsigned long long k = src[j];
        if (k < b[7]) {
            int pos = 7;
            while (pos > 0 && k < b[pos - 1]) { b[pos] = b[pos - 1]; pos--; }
            b[pos] = k;
        }
    }
    #pragma unroll
    for (int i = 0; i < 8; i++) g_cand8[(size_t)tok * 8 + i] = b[i];
}

// ---------------------------------------------------------------------------
// Refine (exact fp32, 8 candidates) + rotation, coalesced.
// ---------------------------------------------------------------------------
__global__ __launch_bounds__(256) void rotate_kernel(const float* __restrict__ z,
                                                     float* __restrict__ out,
                                                     int out_size) {
    extern __shared__ char rsm[];
    float (*zt)[257] = (float(*)[257])rsm;
    float (*et)[257] = (float(*)[257])(rsm + R_SM_ET);
    float (*ssc)[8]  = (float(*)[8]) (rsm + R_SM_SC);
    const int tid = threadIdx.x, lane = tid & 31, wid = tid >> 5;
    const int t0 = blockIdx.x * 32;
    const int bb = t0 >> 10, hw0 = t0 & (HW - 1);
    const float* zb = z + (size_t)bb * CDIM * HW + hw0;

    #pragma unroll
    for (int i = 0; i < 32; i++) {
        const int c = wid * 32 + i;
        zt[lane][c] = zb[(size_t)c * HW + lane];
    }
    __syncthreads();

    for (int q = 0; q < 4; q++) {
        const int tt = wid * 4 + q;
        const int gtok = t0 + tt;
        int cand[8];
        #pragma unroll
        for (int i = 0; i < 8; i++)
            cand[i] = (int)(g_cand8[(size_t)gtok * 8 + i] & 0xFFFFFFFFULL);
        float p[8] = {0.f,0.f,0.f,0.f,0.f,0.f,0.f,0.f};
        #pragma unroll
        for (int j = 0; j < 8; j++) {
            const int c = lane + 32 * j;
            const float zv = zt[tt][c];
            #pragma unroll
            for (int i = 0; i < 8; i++)
                p[i] = fmaf(zv, __ldg(&g_emb[(size_t)cand[i] * CDIM + c]), p[i]);
        }
        #pragma unroll
        for (int i = 0; i < 8; i++)
            #pragma unroll
            for (int off = 16; off > 0; off >>= 1)
                p[i] += __shfl_xor_sync(0xFFFFFFFFu, p[i], off);
        unsigned long long bk = ~0ULL;
        float zebest = 0.0f;
        #pragma unroll
        for (int i = 0; i < 8; i++) {
            const float s = fmaf(-2.0f, p[i], __ldg(&g_e2[cand[i]]));
            const unsigned long long key =
                ((unsigned long long)fkey(s) << 32) | (unsigned)cand[i];
            if (key < bk) { bk = key; zebest = p[i]; }
        }
        const int idx = (int)(bk & 0xFFFFFFFFULL);

        float zz = 0.0f;
        #pragma unroll
        for (int j = 0; j < 8; j++) {
            const int c = lane + 32 * j;
            const float ev = __ldg(&g_emb[(size_t)idx * CDIM + c]);
            et[tt][c] = ev;
            const float zv = zt[tt][c];
            zz = fmaf(zv, zv, zz);
        }
        #pragma unroll
        for (int off = 16; off > 0; off >>= 1)
            zz += __shfl_xor_sync(0xFFFFFFFFu, zz, off);
        const float ZZ = zz, ZE = zebest, EE = __ldg(&g_e2[idx]);
        if (lane == 0) {
            const float ns = sqrtf(ZZ), ntg = sqrtf(EE);
            const float rdns = 1.0f / (ns + EPSF), rdnt = 1.0f / (ntg + EPSF);
            const float uq2 = ZZ*rdns*rdns + 2.0f*ZE*rdns*rdnt + EE*rdnt*rdnt;
            const float rdnw = 1.0f / (sqrtf(uq2) + EPSF);
            ssc[tt][0] = rdns;
            ssc[tt][1] = rdnt;
            ssc[tt][2] = rdnw;
            ssc[tt][3] = (ZZ * rdns + ZE * rdnt) * rdnw;
            ssc[tt][4] = ZZ * rdns;
            ssc[tt][5] = ntg * rdns;
            if (out_size > ZQ_ELEMS) {
                const float sq = ZZ - 2.0f * ZE + EE;
                atomicAdd(&out[ZQ_ELEMS], 1.25f * sq / (float)ZQ_ELEMS);
            }
            if (out_size >= ZQ_ELEMS + 1 + NTOK)
                out[ZQ_ELEMS + 1 + gtok] = (float)idx;
        }
    }
    __syncthreads();

    const float rdns = ssc[lane][0], rdnt = ssc[lane][1], rdnw = ssc[lane][2];
    const float sw = ssc[lane][3], su = ssc[lane][4], scale = ssc[lane][5];
    float* ob = out + (size_t)bb * CDIM * HW + hw0;
    #pragma unroll
    for (int i = 0; i < 32; i++) {
        const int c = wid * 32 + i;
        const float zc = zt[lane][c];
        const float ec = et[lane][c];
        const float q_ch = ec * rdnt;
        const float w_ch = (zc * rdns + q_ch) * rdnw;
        const float rot = zc - 2.0f * sw * w_ch + 2.0f * su * q_ch;
        ob[(size_t)c * HW + lane] = rot * scale;
    }
}

extern "C" void kernel_launch(void* const* d_in, const int* in_sizes, int n_in,
                              void* d_out, int out_size) {
    const float* z  = (const float*)d_in[0];   // (8,256,32,32)
    const float* cb = (const float*)d_in[1];   // (16384,256)
    const float* W  = (const float*)d_in[2];   // (256,256)
    float* out = (float*)d_out;

    cudaFuncSetAttribute(dist_kernel,
                         cudaFuncAttributeMaxDynamicSharedMemorySize, SMEM_DYN_D);
    cudaFuncSetAttribute(rotate_kernel,
                         cudaFuncAttributeMaxDynamicSharedMemorySize, SMEM_ROT);

    zsplit_kernel<<<dim3(4, NTOK / 64), 256>>>(z);
    emb_kernel<<<dim3(4, NE / 64), 256>>>(cb, W);
    e2_kernel<<<NE / 8, 256>>>(out, out_size);
    dist_kernel<<<DGRID, DTHREADS, SMEM_DYN_D>>>(out);
    merge8_kernel<<<NTOK / 256, 256>>>();
    rotate_kernel<<<NTOK / 32, 256, SMEM_ROT>>>(z, out, out_size);
}

// round 14
// speedup vs baseline: 2.0979x; 1.0381x over previous
#include <cuda_runtime.h>
#include <cuda_fp16.h>
#include <cstdint>
#include <math.h>

#define NTOK 8192
#define NE   16384
#define CDIM 256
#define HW   1024
#define ZQ_ELEMS (NTOK*CDIM)
#define EPSF 1e-6f

#define MTILE 128
#define NTILE 128
#define NSB 16                  // code blocks of 1024 codes
#define NT_PER_ITEM 8           // 8 x 128-code tiles per item
#define NITEMS (64*NSB)         // 64 token tiles x 16 blocks = 1024
#define DGRID 152
#define DTHREADS 256            // 8 warps: 2(M) x 4(N), warp tile 64x32

// dist smem: A plane (full K) + 2 full-K B buffers + e2 double buffer + item slot
#define AROW 528u
#define BROW 528u
#define OFF_B(buf) ((unsigned)(buf)*67584u)     // 128*528 per buf
#define OFF_E2 135168u                          // 2 x 512B
#define OFF_AH 136192u
#define OFF_ITEM 203776u
#define SMEM_DYN_D 203792

// rotate smem
#define R_SM_ET 32992u
#define R_SM_SC (2u*32992u)
#define SMEM_ROT (2*32992 + 1024 + 256)

// ---------------- device scratch (static, allocation-free) ----------------
__device__ float g_emb[NE * CDIM];            // fp32 emb = cb @ W^T (exact)
__device__ float g_e2[NE];                    // |emb_j|^2 (atomic partials)
__device__ unsigned short g_emb_h[NE * CDIM]; // fp16 plane
__device__ unsigned short g_z_h[NTOK * CDIM]; // fp16 plane
__device__ unsigned long long g_cand[NTOK * 32];  // best-2 per (tok, block)
__device__ int g_ctr;                             // work-steal counter

// ---------------- helpers --------------------------------------------------
__device__ __forceinline__ uint32_t smem_u32(const void* p) {
    uint32_t a;
    asm("{ .reg .u64 t; cvta.to.shared.u64 t, %1; cvt.u32.u64 %0, t; }"
        : "=r"(a) : "l"(p));
    return a;
}
__device__ __forceinline__ void cp16(uint32_t dst, const void* src) {
    asm volatile("cp.async.cg.shared.global [%0], [%1], 16;" :: "r"(dst), "l"(src));
}
__device__ __forceinline__ void cp_commit() { asm volatile("cp.async.commit_group;"); }
__device__ __forceinline__ void cp_wait1()  { asm volatile("cp.async.wait_group 1;"); }
#define LDSM4(r0,r1,r2,r3,addr) \
    asm volatile("ldmatrix.sync.aligned.m8n8.x4.shared.b16 {%0,%1,%2,%3}, [%4];" \
        : "=r"(r0), "=r"(r1), "=r"(r2), "=r"(r3) : "r"(addr))
__device__ __forceinline__ void mma16816h(uint32_t* c, const uint32_t* a,
                                          uint32_t b0, uint32_t b1) {
    asm volatile(
        "mma.sync.aligned.m16n8k16.row.col.f16.f16.f16.f16 "
        "{%0,%1}, {%2,%3,%4,%5}, {%6,%7}, {%0,%1};"
        : "+r"(c[0]), "+r"(c[1])
        : "r"(a[0]), "r"(a[1]), "r"(a[2]), "r"(a[3]), "r"(b0), "r"(b1));
}
__device__ __forceinline__ float2 h2f2(uint32_t v) {
    __half2 h = *reinterpret_cast<__half2*>(&v);
    return __half22float2(h);
}
__device__ __forceinline__ unsigned int fkey(float f) {
    unsigned int u = __float_as_uint(f);
    return (u & 0x80000000u) ? ~u : (u | 0x80000000u);
}
__device__ __forceinline__ unsigned short hfu(float f) {
    return __half_as_ushort(__float2half_rn(f));
}
__device__ __forceinline__ void ins2(unsigned long long* b, unsigned long long k) {
    if (k < b[1]) {
        if (k < b[0]) { b[1] = b[0]; b[0] = k; } else b[1] = k;
    }
}
__device__ __forceinline__ unsigned long long
wmin64(unsigned long long v) {
    #pragma unroll
    for (int off = 16; off > 0; off >>= 1) {
        const unsigned long long o = __shfl_xor_sync(0xFFFFFFFFu, v, off);
        if (o < v) v = o;
    }
    return v;
}

// ---------------------------------------------------------------------------
// z split: fp32 z -> fp16 plane, token-major rows.
// Also zeroes g_e2, resets work counter, zeroes loss slot.
// ---------------------------------------------------------------------------
__global__ __launch_bounds__(256) void zsplit_kernel(const float* __restrict__ z,
                                                     float* out, int out_size) {
    __shared__ float s[64][65];
    const int tid = threadIdx.x;
    if (blockIdx.x == 0 && blockIdx.y < 64)
        g_e2[blockIdx.y * 256 + tid] = 0.0f;
    if (blockIdx.x == 0 && blockIdx.y == 0 && tid == 0) {
        g_ctr = 0;
        if (out_size > ZQ_ELEMS) out[ZQ_ELEMS] = 0.0f;
    }
    const int t0 = blockIdx.y * 64;
    const int p0 = blockIdx.x * 32;
    const int bb = t0 >> 10;
    const int hw0 = t0 & (HW - 1);
    const float* zb = z + (size_t)bb * CDIM * HW + hw0;

    #pragma unroll
    for (int r = 0; r < 16; r++) {
        const int id = tid + 256 * r;
        const int kk = id >> 6, tt = id & 63;
        s[kk][tt] = zb[(size_t)(2 * p0 + kk) * HW + tt];
    }
    __syncthreads();
    #pragma unroll
    for (int r = 0; r < 8; r++) {
        const int id = tid + 256 * r;
        const int tt = id >> 5, pp = id & 31;
        const float z0 = s[2 * pp][tt], z1 = s[2 * pp + 1][tt];
        ((uint32_t*)g_z_h)[(size_t)(t0 + tt) * 128 + p0 + pp] =
            (uint32_t)hfu(z0) | ((uint32_t)hfu(z1) << 16);
    }
}

// ---------------------------------------------------------------------------
// emb = codebook @ W^T fp32 (exact) + fp16 plane + e2 atomic partials
// ---------------------------------------------------------------------------
__global__ __launch_bounds__(256) void emb_kernel(const float* __restrict__ cb,
                                                  const float* __restrict__ W) {
    __shared__ float As[16][68];
    __shared__ float Bs[16][68];
    const int t  = threadIdx.x;
    const int tx = t & 15, ty = t >> 4;
    const int m0 = blockIdx.y * 64;
    const int n0 = blockIdx.x * 64;

    float acc[4][4] = {};
    for (int k0 = 0; k0 < CDIM; k0 += 16) {
        __syncthreads();
        const int kk = t & 15, mm = t >> 4;
        #pragma unroll
        for (int r = 0; r < 4; r++) {
            As[kk][mm + 16*r] = cb[(m0 + mm + 16*r) * CDIM + k0 + kk];
            Bs[kk][mm + 16*r] = W [(n0 + mm + 16*r) * CDIM + k0 + kk];
        }
        __syncthreads();
        #pragma unroll
        for (int k = 0; k < 16; k++) {
            float4 a = *(const float4*)&As[k][ty * 4];
            float4 b = *(const float4*)&Bs[k][tx * 4];
            float av[4] = {a.x, a.y, a.z, a.w};
            float bv[4] = {b.x, b.y, b.z, b.w};
            #pragma unroll
            for (int i = 0; i < 4; i++)
                #pragma unroll
                for (int j = 0; j < 4; j++)
                    acc[i][j] = fmaf(av[i], bv[j], acc[i][j]);
        }
    }
    #pragma unroll
    for (int i = 0; i < 4; i++) {
        const int code = m0 + ty * 4 + i;
        float4 v = make_float4(acc[i][0], acc[i][1], acc[i][2], acc[i][3]);
        const int e0 = code * CDIM + n0 + tx * 4;
        *(float4*)&g_emb[e0] = v;
        uint2 hp;
        hp.x = (uint32_t)hfu(v.x) | ((uint32_t)hfu(v.y) << 16);
        hp.y = (uint32_t)hfu(v.z) | ((uint32_t)hfu(v.w) << 16);
        ((uint2*)g_emb_h)[e0 >> 2] = hp;
        const float e2p = v.x*v.x + v.y*v.y + v.z*v.z + v.w*v.w;
        atomicAdd(&g_e2[code], e2p);
    }
}

// ---------------------------------------------------------------------------
// Distance GEMM: persistent work-stealing. Item = (token tile 128, 1024 codes).
// 8 warps = 2(M) x 4(N), warp tile 64x32, fp16 HMMA. best-2 per (tok, block).
// ---------------------------------------------------------------------------
__global__ __launch_bounds__(DTHREADS, 1) void dist_kernel(float* dummy) {
    extern __shared__ char smem[];
    const uint32_t sb = smem_u32(smem);
    int* s_item = (int*)(smem + OFF_ITEM);
    const int tid  = threadIdx.x;
    const int lane = tid & 31, wid = tid >> 5;
    const int gid  = lane >> 2, tig = lane & 3;
    const int wm = wid & 1, wn = wid >> 1;
    const int m_base = wm * 64, n_base = wn * 32;

    const unsigned st_off = (unsigned)(tid >> 5) * 528u + (unsigned)(tid & 31) * 16u;
    const size_t   src_off = (size_t)(tid >> 5) * 256 + (size_t)(tid & 31) * 8;

    const uint32_t aoffA = (uint32_t)((m_base + ((lane >> 3) & 1) * 8 + (lane & 7)) * AROW
                                      + ((lane >> 4) * 8) * 2);
    const uint32_t aAh = sb + OFF_AH + aoffA;
    const uint32_t boffB = (uint32_t)((n_base + (lane >> 4) * 8 + (lane & 7)) * BROW
                                      + (((lane >> 3) & 1) * 8) * 2);

    int last_tt = -1;

    for (;;) {
        if (tid == 0) *s_item = atomicAdd(&g_ctr, 1);
        __syncthreads();
        const int item = *s_item;
        if (item >= NITEMS) break;
        const int tt = item >> 4, sbk = item & (NSB - 1);
        const int m0 = tt * MTILE;
        const int nbase = sbk * 1024;

        if (tt != last_tt) {
            const unsigned short* zh = g_z_h + (size_t)m0 * CDIM + src_off;
            #pragma unroll
            for (int r = 0; r < 16; r++)
                cp16(sb + OFF_AH + st_off + (unsigned)r * (8u * 528u),
                     zh + (size_t)r * 2048);
            last_tt = tt;
        }
        {
            const unsigned short* bh0 = g_emb_h + (size_t)nbase * CDIM + src_off;
            #pragma unroll
            for (int r = 0; r < 16; r++)
                cp16(sb + OFF_B(0) + st_off + (unsigned)r * (8u * 528u),
                     bh0 + (size_t)r * 2048);
            if (tid < 32) cp16(sb + OFF_E2 + (unsigned)tid * 16u, g_e2 + nbase + tid * 4);
            cp_commit();
        }

        unsigned long long bL[8][2];
        #pragma unroll
        for (int i = 0; i < 8; i++) { bL[i][0] = ~0ULL; bL[i][1] = ~0ULL; }

        const unsigned short* bsrc = g_emb_h + (size_t)(nbase + NTILE) * CDIM + src_off;
        const float* e2src = g_e2 + nbase + NTILE + (tid < 32 ? tid * 4 : 0);

        for (int nt = 0; nt < NT_PER_ITEM; nt++) {
            const int buf = nt & 1;
            if (nt + 1 < NT_PER_ITEM) {
                const uint32_t dstb = sb + OFF_B(buf ^ 1) + st_off;
                #pragma unroll
                for (int r = 0; r < 16; r++)
                    cp16(dstb + (unsigned)r * (8u * 528u), bsrc + (size_t)r * 2048);
                if (tid < 32)
                    cp16(sb + OFF_E2 + (unsigned)(buf ^ 1) * 512u + (unsigned)tid * 16u,
                         e2src);
            }
            cp_commit();
            cp_wait1();
            __syncthreads();
            bsrc += (size_t)NTILE * CDIM;
            e2src += NTILE;

            uint32_t acc[4][4][2] = {};
            const uint32_t Bh = sb + OFF_B(buf) + boffB;
            #pragma unroll
            for (int s = 0; s < 16; s++) {
                uint32_t ah[4][4], bh[2][4];
                const uint32_t ko = (uint32_t)(s * 32);
                #pragma unroll
                for (int ma = 0; ma < 4; ma++)
                    LDSM4(ah[ma][0], ah[ma][1], ah[ma][2], ah[ma][3],
                          aAh + (uint32_t)(ma * 16) * AROW + ko);
                #pragma unroll
                for (int nb = 0; nb < 2; nb++)
                    LDSM4(bh[nb][0], bh[nb][1], bh[nb][2], bh[nb][3],
                          Bh + (uint32_t)(nb * 16) * BROW + ko);
                #pragma unroll
                for (int nb = 0; nb < 2; nb++)
                    #pragma unroll
                    for (int h = 0; h < 2; h++)
                        #pragma unroll
                        for (int ma = 0; ma < 4; ma++)
                            mma16816h(acc[ma][nb*2+h], ah[ma], bh[nb][2*h], bh[nb][2*h+1]);
            }

            {
                const float* e2p = (const float*)(smem + OFF_E2 + (size_t)buf * 512);
                const int n0 = nbase + nt * NTILE;
                #pragma unroll
                for (int na = 0; na < 4; na++) {
                    const int cc = n_base + na * 8 + tig * 2;
                    const float e2a = e2p[cc], e2b = e2p[cc + 1];
                    const int c0 = n0 + cc;
                    #pragma unroll
                    for (int ma = 0; ma < 4; ma++) {
                        {
                            const float2 v = h2f2(acc[ma][na][0]);
                            const float s0 = fmaf(-2.0f, v.x, e2a);
                            const float s1 = fmaf(-2.0f, v.y, e2b);
                            const float sm = fminf(s0, s1);
                            const unsigned cm = (s0 <= s1) ? (unsigned)c0 : (unsigned)(c0 + 1);
                            ins2(bL[ma * 2 + 0], ((unsigned long long)fkey(sm) << 32) | cm);
                        }
                        {
                            const float2 v = h2f2(acc[ma][na][1]);
                            const float s0 = fmaf(-2.0f, v.x, e2a);
                            const float s1 = fmaf(-2.0f, v.y, e2b);
                            const float sm = fminf(s0, s1);
                            const unsigned cm = (s0 <= s1) ? (unsigned)c0 : (unsigned)(c0 + 1);
                            ins2(bL[ma * 2 + 1], ((unsigned long long)fkey(sm) << 32) | cm);
                        }
                    }
                }
            }
            __syncthreads();
        }

        // ---- per-item merge: tig lanes -> smem -> best-2 per token row ----
        #pragma unroll
        for (int off = 1; off <= 2; off <<= 1) {
            #pragma unroll
            for (int l = 0; l < 8; l++) {
                #pragma unroll
                for (int e = 0; e < 2; e++) {
                    const unsigned long long ok = __shfl_xor_sync(0xFFFFFFFFu, bL[l][e], off);
                    ins2(bL[l], ok);
                }
            }
        }
        __syncthreads();
        unsigned long long* red = (unsigned long long*)smem;  // 128 x 4 wn x 2
        if (tig == 0) {
            #pragma unroll
            for (int l = 0; l < 8; l++) {
                const int row = m_base + (l >> 1) * 16 + gid + (l & 1) * 8;
                red[(row * 4 + wn) * 2 + 0] = bL[l][0];
                red[(row * 4 + wn) * 2 + 1] = bL[l][1];
            }
        }
        __syncthreads();
        if (tid < 128) {
            unsigned long long b[2] = {~0ULL, ~0ULL};
            #pragma unroll
            for (int w = 0; w < 4; w++) {
                ins2(b, red[(tid * 4 + w) * 2 + 0]);
                ins2(b, red[(tid * 4 + w) * 2 + 1]);
            }
            const size_t slot = ((size_t)(m0 + tid) * NSB + sbk) * 2;
            g_cand[slot + 0] = b[0];
            g_cand[slot + 1] = b[1];
        }
        __syncthreads();
    }
}

// ---------------------------------------------------------------------------
// Merge 32 keys -> 8 (warp min-extract) + exact fp32 refine + rotation.
// Block = 32 consecutive tokens; coalesced loads/stores.
// ---------------------------------------------------------------------------
__global__ __launch_bounds__(256) void rotate_kernel(const float* __restrict__ z,
                                                     float* __restrict__ out,
                                                     int out_size) {
    extern __shared__ char rsm[];
    float (*zt)[257] = (float(*)[257])rsm;
    float (*et)[257] = (float(*)[257])(rsm + R_SM_ET);
    float (*ssc)[8]  = (float(*)[8]) (rsm + R_SM_SC);
    const int tid = threadIdx.x, lane = tid & 31, wid = tid >> 5;
    const int t0 = blockIdx.x * 32;
    const int bb = t0 >> 10, hw0 = t0 & (HW - 1);
    const float* zb = z + (size_t)bb * CDIM * HW + hw0;

    #pragma unroll
    for (int i = 0; i < 32; i++) {
        const int c = wid * 32 + i;
        zt[lane][c] = zb[(size_t)c * HW + lane];
    }
    __syncthreads();

    for (int q = 0; q < 4; q++) {
        const int tt = wid * 4 + q;
        const int gtok = t0 + tt;

        // merge: 32 block-keys -> best-8 (keys unique; min-extract)
        int cand[8];
        {
            unsigned long long k = g_cand[(size_t)gtok * 32 + lane];
            #pragma unroll
            for (int i = 0; i < 8; i++) {
                const unsigned long long m = wmin64(k);
                cand[i] = (int)(m & 0xFFFFFFFFULL);
                if (k == m) k = ~0ULL;
            }
        }

        float p[8] = {0.f,0.f,0.f,0.f,0.f,0.f,0.f,0.f};
        #pragma unroll
        for (int j = 0; j < 8; j++) {
            const int c = lane + 32 * j;
            const float zv = zt[tt][c];
            #pragma unroll
            for (int i = 0; i < 8; i++)
                p[i] = fmaf(zv, __ldg(&g_emb[(size_t)cand[i] * CDIM + c]), p[i]);
        }
        #pragma unroll
        for (int i = 0; i < 8; i++)
            #pragma unroll
            for (int off = 16; off > 0; off >>= 1)
                p[i] += __shfl_xor_sync(0xFFFFFFFFu, p[i], off);
        unsigned long long bk = ~0ULL;
        float zebest = 0.0f;
        #pragma unroll
        for (int i = 0; i < 8; i++) {
            const float s = fmaf(-2.0f, p[i], __ldg(&g_e2[cand[i]]));
            const unsigned long long key =
                ((unsigned long long)fkey(s) << 32) | (unsigned)cand[i];
            if (key < bk) { bk = key; zebest = p[i]; }
        }
        const int idx = (int)(bk & 0xFFFFFFFFULL);

        float zz = 0.0f;
        #pragma unroll
        for (int j = 0; j < 8; j++) {
            const int c = lane + 32 * j;
            const float ev = __ldg(&g_emb[(size_t)idx * CDIM + c]);
            et[tt][c] = ev;
            const float zv = zt[tt][c];
            zz = fmaf(zv, zv, zz);
        }
        #pragma unroll
        for (int off = 16; off > 0; off >>= 1)
            zz += __shfl_xor_sync(0xFFFFFFFFu, zz, off);
        const float ZZ = zz, ZE = zebest, EE = __ldg(&g_e2[idx]);
        if (lane == 0) {
            const float ns = sqrtf(ZZ), ntg = sqrtf(EE);
            const float rdns = 1.0f / (ns + EPSF), rdnt = 1.0f / (ntg + EPSF);
            const float uq2 = ZZ*rdns*rdns + 2.0f*ZE*rdns*rdnt + EE*rdnt*rdnt;
            const float rdnw = 1.0f / (sqrtf(uq2) + EPSF);
            ssc[tt][0] = rdns;
            ssc[tt][1] = rdnt;
            ssc[tt][2] = rdnw;
            ssc[tt][3] = (ZZ * rdns + ZE * rdnt) * rdnw;
            ssc[tt][4] = ZZ * rdns;
            ssc[tt][5] = ntg * rdns;
            if (out_size > ZQ_ELEMS) {
                const float sq = ZZ - 2.0f * ZE + EE;
                atomicAdd(&out[ZQ_ELEMS], 1.25f * sq / (float)ZQ_ELEMS);
            }
            if (out_size >= ZQ_ELEMS + 1 + NTOK)
                out[ZQ_ELEMS + 1 + gtok] = (float)idx;
        }
    }
    __syncthreads();

    const float rdns = ssc[lane][0], rdnt = ssc[lane][1], rdnw = ssc[lane][2];
    const float sw = ssc[lane][3], su = ssc[lane][4], scale = ssc[lane][5];
    float* ob = out + (size_t)bb * CDIM * HW + hw0;
    #pragma unroll
    for (int i = 0; i < 32; i++) {
        const int c = wid * 32 + i;
        const float zc = zt[lane][c];
        const float ec = et[lane][c];
        const float q_ch = ec * rdnt;
        const float w_ch = (zc * rdns + q_ch) * rdnw;
        const float rot = zc - 2.0f * sw * w_ch + 2.0f * su * q_ch;
        ob[(size_t)c * HW + lane] = rot * scale;
    }
}

extern "C" void kernel_launch(void* const* d_in, const int* in_sizes, int n_in,
                              void* d_out, int out_size) {
    const float* z  = (const float*)d_in[0];   // (8,256,32,32)
    const float* cb = (const float*)d_in[1];   // (16384,256)
    const float* W  = (const float*)d_in[2];   // (256,256)
    float* out = (float*)d_out;

    cudaFuncSetAttribute(dist_kernel,
                         cudaFuncAttributeMaxDynamicSharedMemorySize, SMEM_DYN_D);
    cudaFuncSetAttribute(rotate_kernel,
                         cudaFuncAttributeMaxDynamicSharedMemorySize, SMEM_ROT);

    zsplit_kernel<<<dim3(4, NTOK / 64), 256>>>(z, out, out_size);
    emb_kernel<<<dim3(4, NE / 64), 256>>>(cb, W);
    dist_kernel<<<DGRID, DTHREADS, SMEM_DYN_D>>>(out);
    rotate_kernel<<<NTOK / 32, 256, SMEM_ROT>>>(z, out, out_size);
}

// round 15
// speedup vs baseline: 2.1202x; 1.0106x over previous
#include <cuda_runtime.h>
#include <cuda_fp16.h>
#include <cstdint>
#include <math.h>

#define NTOK 8192
#define NE   16384
#define CDIM 256
#define HW   1024
#define ZQ_ELEMS (NTOK*CDIM)
#define EPSF 1e-6f

#define MTILE 128
#define NTILE 128
#define NSB 16                  // code blocks of 1024 codes
#define NT_PER_ITEM 8           // 8 x 128-code tiles per item
#define NITEMS (64*NSB)         // 64 token tiles x 16 blocks = 1024
#define DGRID 152
#define DTHREADS 256            // 8 warps: 2(M) x 4(N), warp tile 64x32

// dist smem: A plane (full K) + 2 full-K B buffers + e2 double buffer + item slot
#define AROW 528u
#define BROW 528u
#define OFF_B(buf) ((unsigned)(buf)*67584u)     // 128*528 per buf
#define OFF_E2 135168u                          // 2 x 512B
#define OFF_AH 136192u
#define OFF_ITEM 203776u
#define SMEM_DYN_D 203792

// rotate smem
#define R_SM_ET 32992u
#define R_SM_SC (2u*32992u)
#define SMEM_ROT (2*32992 + 1024 + 256)
#define RTHREADS 512            // 16 warps: 2 tokens per warp in refine

// ---------------- device scratch (static, allocation-free) ----------------
__device__ float g_emb[NE * CDIM];            // fp32 emb = cb @ W^T (exact)
__device__ float g_e2[NE];                    // |emb_j|^2 (atomic partials)
__device__ unsigned short g_emb_h[NE * CDIM]; // fp16 plane
__device__ unsigned short g_z_h[NTOK * CDIM]; // fp16 plane
__device__ unsigned long long g_cand[NTOK * 32];  // best-2 per (tok, block)
__device__ int g_ctr;                             // work-steal counter

// ---------------- helpers --------------------------------------------------
__device__ __forceinline__ uint32_t smem_u32(const void* p) {
    uint32_t a;
    asm("{ .reg .u64 t; cvta.to.shared.u64 t, %1; cvt.u32.u64 %0, t; }"
        : "=r"(a) : "l"(p));
    return a;
}
__device__ __forceinline__ void cp16(uint32_t dst, const void* src) {
    asm volatile("cp.async.cg.shared.global [%0], [%1], 16;" :: "r"(dst), "l"(src));
}
__device__ __forceinline__ void cp_commit() { asm volatile("cp.async.commit_group;"); }
__device__ __forceinline__ void cp_wait1()  { asm volatile("cp.async.wait_group 1;"); }
#define LDSM4(r0,r1,r2,r3,addr) \
    asm volatile("ldmatrix.sync.aligned.m8n8.x4.shared.b16 {%0,%1,%2,%3}, [%4];" \
        : "=r"(r0), "=r"(r1), "=r"(r2), "=r"(r3) : "r"(addr))
__device__ __forceinline__ void mma16816h(uint32_t* c, const uint32_t* a,
                                          uint32_t b0, uint32_t b1) {
    asm volatile(
        "mma.sync.aligned.m16n8k16.row.col.f16.f16.f16.f16 "
        "{%0,%1}, {%2,%3,%4,%5}, {%6,%7}, {%0,%1};"
        : "+r"(c[0]), "+r"(c[1])
        : "r"(a[0]), "r"(a[1]), "r"(a[2]), "r"(a[3]), "r"(b0), "r"(b1));
}
__device__ __forceinline__ float2 h2f2(uint32_t v) {
    __half2 h = *reinterpret_cast<__half2*>(&v);
    return __half22float2(h);
}
__device__ __forceinline__ unsigned int fkey(float f) {
    unsigned int u = __float_as_uint(f);
    return (u & 0x80000000u) ? ~u : (u | 0x80000000u);
}
__device__ __forceinline__ unsigned short hfu(float f) {
    return __half_as_ushort(__float2half_rn(f));
}
__device__ __forceinline__ void ins2(unsigned long long* b, unsigned long long k) {
    if (k < b[1]) {
        if (k < b[0]) { b[1] = b[0]; b[0] = k; } else b[1] = k;
    }
}
__device__ __forceinline__ unsigned long long
wmin64(unsigned long long v) {
    #pragma unroll
    for (int off = 16; off > 0; off >>= 1) {
        const unsigned long long o = __shfl_xor_sync(0xFFFFFFFFu, v, off);
        if (o < v) v = o;
    }
    return v;
}

// ---------------------------------------------------------------------------
// z split: fp32 z -> fp16 plane, token-major rows.
// Also zeroes g_e2, resets work counter, zeroes loss slot.
// ---------------------------------------------------------------------------
__global__ __launch_bounds__(256) void zsplit_kernel(const float* __restrict__ z,
                                                     float* out, int out_size) {
    __shared__ float s[64][65];
    const int tid = threadIdx.x;
    if (blockIdx.x == 0 && blockIdx.y < 64)
        g_e2[blockIdx.y * 256 + tid] = 0.0f;
    if (blockIdx.x == 0 && blockIdx.y == 0 && tid == 0) {
        g_ctr = 0;
        if (out_size > ZQ_ELEMS) out[ZQ_ELEMS] = 0.0f;
    }
    const int t0 = blockIdx.y * 64;
    const int p0 = blockIdx.x * 32;
    const int bb = t0 >> 10;
    const int hw0 = t0 & (HW - 1);
    const float* zb = z + (size_t)bb * CDIM * HW + hw0;

    #pragma unroll
    for (int r = 0; r < 16; r++) {
        const int id = tid + 256 * r;
        const int kk = id >> 6, tt = id & 63;
        s[kk][tt] = zb[(size_t)(2 * p0 + kk) * HW + tt];
    }
    __syncthreads();
    #pragma unroll
    for (int r = 0; r < 8; r++) {
        const int id = tid + 256 * r;
        const int tt = id >> 5, pp = id & 31;
        const float z0 = s[2 * pp][tt], z1 = s[2 * pp + 1][tt];
        ((uint32_t*)g_z_h)[(size_t)(t0 + tt) * 128 + p0 + pp] =
            (uint32_t)hfu(z0) | ((uint32_t)hfu(z1) << 16);
    }
}

// ---------------------------------------------------------------------------
// emb = codebook @ W^T fp32 (exact) + fp16 plane + e2 atomic partials
// ---------------------------------------------------------------------------
__global__ __launch_bounds__(256) void emb_kernel(const float* __restrict__ cb,
                                                  const float* __restrict__ W) {
    __shared__ float As[16][68];
    __shared__ float Bs[16][68];
    const int t  = threadIdx.x;
    const int tx = t & 15, ty = t >> 4;
    const int m0 = blockIdx.y * 64;
    const int n0 = blockIdx.x * 64;

    float acc[4][4] = {};
    for (int k0 = 0; k0 < CDIM; k0 += 16) {
        __syncthreads();
        const int kk = t & 15, mm = t >> 4;
        #pragma unroll
        for (int r = 0; r < 4; r++) {
            As[kk][mm + 16*r] = cb[(m0 + mm + 16*r) * CDIM + k0 + kk];
            Bs[kk][mm + 16*r] = W [(n0 + mm + 16*r) * CDIM + k0 + kk];
        }
        __syncthreads();
        #pragma unroll
        for (int k = 0; k < 16; k++) {
            float4 a = *(const float4*)&As[k][ty * 4];
            float4 b = *(const float4*)&Bs[k][tx * 4];
            float av[4] = {a.x, a.y, a.z, a.w};
            float bv[4] = {b.x, b.y, b.z, b.w};
            #pragma unroll
            for (int i = 0; i < 4; i++)
                #pragma unroll
                for (int j = 0; j < 4; j++)
                    acc[i][j] = fmaf(av[i], bv[j], acc[i][j]);
        }
    }
    #pragma unroll
    for (int i = 0; i < 4; i++) {
        const int code = m0 + ty * 4 + i;
        float4 v = make_float4(acc[i][0], acc[i][1], acc[i][2], acc[i][3]);
        const int e0 = code * CDIM + n0 + tx * 4;
        *(float4*)&g_emb[e0] = v;
        uint2 hp;
        hp.x = (uint32_t)hfu(v.x) | ((uint32_t)hfu(v.y) << 16);
        hp.y = (uint32_t)hfu(v.z) | ((uint32_t)hfu(v.w) << 16);
        ((uint2*)g_emb_h)[e0 >> 2] = hp;
        const float e2p = v.x*v.x + v.y*v.y + v.z*v.z + v.w*v.w;
        atomicAdd(&g_e2[code], e2p);
    }
}

// ---------------------------------------------------------------------------
// Distance GEMM: persistent work-stealing. Item = (token tile 128, 1024 codes).
// 8 warps = 2(M) x 4(N), warp tile 64x32, fp16 HMMA. best-2 per (tok, block).
// ---------------------------------------------------------------------------
__global__ __launch_bounds__(DTHREADS, 1) void dist_kernel(float* dummy) {
    extern __shared__ char smem[];
    const uint32_t sb = smem_u32(smem);
    int* s_item = (int*)(smem + OFF_ITEM);
    const int tid  = threadIdx.x;
    const int lane = tid & 31, wid = tid >> 5;
    const int gid  = lane >> 2, tig = lane & 3;
    const int wm = wid & 1, wn = wid >> 1;
    const int m_base = wm * 64, n_base = wn * 32;

    const unsigned st_off = (unsigned)(tid >> 5) * 528u + (unsigned)(tid & 31) * 16u;
    const size_t   src_off = (size_t)(tid >> 5) * 256 + (size_t)(tid & 31) * 8;

    const uint32_t aoffA = (uint32_t)((m_base + ((lane >> 3) & 1) * 8 + (lane & 7)) * AROW
                                      + ((lane >> 4) * 8) * 2);
    const uint32_t aAh = sb + OFF_AH + aoffA;
    const uint32_t boffB = (uint32_t)((n_base + (lane >> 4) * 8 + (lane & 7)) * BROW
                                      + (((lane >> 3) & 1) * 8) * 2);

    int last_tt = -1;

    for (;;) {
        if (tid == 0) *s_item = atomicAdd(&g_ctr, 1);
        __syncthreads();
        const int item = *s_item;
        if (item >= NITEMS) break;
        const int tt = item >> 4, sbk = item & (NSB - 1);
        const int m0 = tt * MTILE;
        const int nbase = sbk * 1024;

        if (tt != last_tt) {
            const unsigned short* zh = g_z_h + (size_t)m0 * CDIM + src_off;
            #pragma unroll
            for (int r = 0; r < 16; r++)
                cp16(sb + OFF_AH + st_off + (unsigned)r * (8u * 528u),
                     zh + (size_t)r * 2048);
            last_tt = tt;
        }
        {
            const unsigned short* bh0 = g_emb_h + (size_t)nbase * CDIM + src_off;
            #pragma unroll
            for (int r = 0; r < 16; r++)
                cp16(sb + OFF_B(0) + st_off + (unsigned)r * (8u * 528u),
                     bh0 + (size_t)r * 2048);
            if (tid < 32) cp16(sb + OFF_E2 + (unsigned)tid * 16u, g_e2 + nbase + tid * 4);
            cp_commit();
        }

        unsigned long long bL[8][2];
        #pragma unroll
        for (int i = 0; i < 8; i++) { bL[i][0] = ~0ULL; bL[i][1] = ~0ULL; }

        const unsigned short* bsrc = g_emb_h + (size_t)(nbase + NTILE) * CDIM + src_off;
        const float* e2src = g_e2 + nbase + NTILE + (tid < 32 ? tid * 4 : 0);

        for (int nt = 0; nt < NT_PER_ITEM; nt++) {
            const int buf = nt & 1;
            if (nt + 1 < NT_PER_ITEM) {
                const uint32_t dstb = sb + OFF_B(buf ^ 1) + st_off;
                #pragma unroll
                for (int r = 0; r < 16; r++)
                    cp16(dstb + (unsigned)r * (8u * 528u), bsrc + (size_t)r * 2048);
                if (tid < 32)
                    cp16(sb + OFF_E2 + (unsigned)(buf ^ 1) * 512u + (unsigned)tid * 16u,
                         e2src);
            }
            cp_commit();
            cp_wait1();
            __syncthreads();
            bsrc += (size_t)NTILE * CDIM;
            e2src += NTILE;

            uint32_t acc[4][4][2] = {};
            const uint32_t Bh = sb + OFF_B(buf) + boffB;
            #pragma unroll
            for (int s = 0; s < 16; s++) {
                uint32_t ah[4][4], bh[2][4];
                const uint32_t ko = (uint32_t)(s * 32);
                #pragma unroll
                for (int ma = 0; ma < 4; ma++)
                    LDSM4(ah[ma][0], ah[ma][1], ah[ma][2], ah[ma][3],
                          aAh + (uint32_t)(ma * 16) * AROW + ko);
                #pragma unroll
                for (int nb = 0; nb < 2; nb++)
                    LDSM4(bh[nb][0], bh[nb][1], bh[nb][2], bh[nb][3],
                          Bh + (uint32_t)(nb * 16) * BROW + ko);
                #pragma unroll
                for (int nb = 0; nb < 2; nb++)
                    #pragma unroll
                    for (int h = 0; h < 2; h++)
                        #pragma unroll
                        for (int ma = 0; ma < 4; ma++)
                            mma16816h(acc[ma][nb*2+h], ah[ma], bh[nb][2*h], bh[nb][2*h+1]);
            }

            {
                const float* e2p = (const float*)(smem + OFF_E2 + (size_t)buf * 512);
                const int n0 = nbase + nt * NTILE;
                #pragma unroll
                for (int na = 0; na < 4; na++) {
                    const int cc = n_base + na * 8 + tig * 2;
                    const float e2a = e2p[cc], e2b = e2p[cc + 1];
                    const int c0 = n0 + cc;
                    #pragma unroll
                    for (int ma = 0; ma < 4; ma++) {
                        {
                            const float2 v = h2f2(acc[ma][na][0]);
                            const float s0 = fmaf(-2.0f, v.x, e2a);
                            const float s1 = fmaf(-2.0f, v.y, e2b);
                            const float sm = fminf(s0, s1);
                            const unsigned cm = (s0 <= s1) ? (unsigned)c0 : (unsigned)(c0 + 1);
                            ins2(bL[ma * 2 + 0], ((unsigned long long)fkey(sm) << 32) | cm);
                        }
                        {
                            const float2 v = h2f2(acc[ma][na][1]);
                            const float s0 = fmaf(-2.0f, v.x, e2a);
                            const float s1 = fmaf(-2.0f, v.y, e2b);
                            const float sm = fminf(s0, s1);
                            const unsigned cm = (s0 <= s1) ? (unsigned)c0 : (unsigned)(c0 + 1);
                            ins2(bL[ma * 2 + 1], ((unsigned long long)fkey(sm) << 32) | cm);
                        }
                    }
                }
            }
            __syncthreads();
        }

        // ---- per-item merge: tig lanes -> smem -> best-2 per token row ----
        #pragma unroll
        for (int off = 1; off <= 2; off <<= 1) {
            #pragma unroll
            for (int l = 0; l < 8; l++) {
                #pragma unroll
                for (int e = 0; e < 2; e++) {
                    const unsigned long long ok = __shfl_xor_sync(0xFFFFFFFFu, bL[l][e], off);
                    ins2(bL[l], ok);
                }
            }
        }
        __syncthreads();
        unsigned long long* red = (unsigned long long*)smem;  // 128 x 4 wn x 2
        if (tig == 0) {
            #pragma unroll
            for (int l = 0; l < 8; l++) {
                const int row = m_base + (l >> 1) * 16 + gid + (l & 1) * 8;
                red[(row * 4 + wn) * 2 + 0] = bL[l][0];
                red[(row * 4 + wn) * 2 + 1] = bL[l][1];
            }
        }
        __syncthreads();
        if (tid < 128) {
            unsigned long long b[2] = {~0ULL, ~0ULL};
            #pragma unroll
            for (int w = 0; w < 4; w++) {
                ins2(b, red[(tid * 4 + w) * 2 + 0]);
                ins2(b, red[(tid * 4 + w) * 2 + 1]);
            }
            const size_t slot = ((size_t)(m0 + tid) * NSB + sbk) * 2;
            g_cand[slot + 0] = b[0];
            g_cand[slot + 1] = b[1];
        }
        __syncthreads();
    }
}

// ---------------------------------------------------------------------------
// Merge 32 keys -> 8 (warp min-extract) + exact fp32 refine + rotation.
// Block = 32 consecutive tokens, 16 warps (2 tokens/warp in refine).
// ---------------------------------------------------------------------------
__global__ __launch_bounds__(RTHREADS) void rotate_kernel(const float* __restrict__ z,
                                                          float* __restrict__ out,
                                                          int out_size) {
    extern __shared__ char rsm[];
    float (*zt)[257] = (float(*)[257])rsm;
    float (*et)[257] = (float(*)[257])(rsm + R_SM_ET);
    float (*ssc)[8]  = (float(*)[8]) (rsm + R_SM_SC);
    const int tid = threadIdx.x, lane = tid & 31, wid = tid >> 5;
    const int t0 = blockIdx.x * 32;
    const int bb = t0 >> 10, hw0 = t0 & (HW - 1);
    const float* zb = z + (size_t)bb * CDIM * HW + hw0;

    // stage z transposed: 16 warps x 16 channels each, lanes = tokens
    #pragma unroll
    for (int i = 0; i < 16; i++) {
        const int c = wid * 16 + i;
        zt[lane][c] = zb[(size_t)c * HW + lane];
    }
    __syncthreads();

    #pragma unroll
    for (int q = 0; q < 2; q++) {
        const int tt = wid * 2 + q;
        const int gtok = t0 + tt;

        // merge: 32 block-keys -> best-8 (keys unique; min-extract)
        int cand[8];
        {
            unsigned long long k = g_cand[(size_t)gtok * 32 + lane];
            #pragma unroll
            for (int i = 0; i < 8; i++) {
                const unsigned long long m = wmin64(k);
                cand[i] = (int)(m & 0xFFFFFFFFULL);
                if (k == m) k = ~0ULL;
            }
        }

        float p[8] = {0.f,0.f,0.f,0.f,0.f,0.f,0.f,0.f};
        #pragma unroll
        for (int j = 0; j < 8; j++) {
            const int c = lane + 32 * j;
            const float zv = zt[tt][c];
            #pragma unroll
            for (int i = 0; i < 8; i++)
                p[i] = fmaf(zv, __ldg(&g_emb[(size_t)cand[i] * CDIM + c]), p[i]);
        }
        #pragma unroll
        for (int i = 0; i < 8; i++)
            #pragma unroll
            for (int off = 16; off > 0; off >>= 1)
                p[i] += __shfl_xor_sync(0xFFFFFFFFu, p[i], off);
        unsigned long long bk = ~0ULL;
        float zebest = 0.0f;
        #pragma unroll
        for (int i = 0; i < 8; i++) {
            const float s = fmaf(-2.0f, p[i], __ldg(&g_e2[cand[i]]));
            const unsigned long long key =
                ((unsigned long long)fkey(s) << 32) | (unsigned)cand[i];
            if (key < bk) { bk = key; zebest = p[i]; }
        }
        const int idx = (int)(bk & 0xFFFFFFFFULL);

        float zz = 0.0f;
        #pragma unroll
        for (int j = 0; j < 8; j++) {
            const int c = lane + 32 * j;
            const float ev = __ldg(&g_emb[(size_t)idx * CDIM + c]);
            et[tt][c] = ev;
            const float zv = zt[tt][c];
            zz = fmaf(zv, zv, zz);
        }
        #pragma unroll
        for (int off = 16; off > 0; off >>= 1)
            zz += __shfl_xor_sync(0xFFFFFFFFu, zz, off);
        const float ZZ = zz, ZE = zebest, EE = __ldg(&g_e2[idx]);
        if (lane == 0) {
            const float ns = sqrtf(ZZ), ntg = sqrtf(EE);
            const float rdns = 1.0f / (ns + EPSF), rdnt = 1.0f / (ntg + EPSF);
            const float uq2 = ZZ*rdns*rdns + 2.0f*ZE*rdns*rdnt + EE*rdnt*rdnt;
            const float rdnw = 1.0f / (sqrtf(uq2) + EPSF);
            ssc[tt][0] = rdns;
            ssc[tt][1] = rdnt;
            ssc[tt][2] = rdnw;
            ssc[tt][3] = (ZZ * rdns + ZE * rdnt) * rdnw;
            ssc[tt][4] = ZZ * rdns;
            ssc[tt][5] = ntg * rdns;
            if (out_size > ZQ_ELEMS) {
                const float sq = ZZ - 2.0f * ZE + EE;
                atomicAdd(&out[ZQ_ELEMS], 1.25f * sq / (float)ZQ_ELEMS);
            }
            if (out_size >= ZQ_ELEMS + 1 + NTOK)
                out[ZQ_ELEMS + 1 + gtok] = (float)idx;
        }
    }
    __syncthreads();

    // output: 16 warps x 16 channels, lanes = tokens -> coalesced stores
    const float rdns = ssc[lane][0], rdnt = ssc[lane][1], rdnw = ssc[lane][2];
    const float sw = ssc[lane][3], su = ssc[lane][4], scale = ssc[lane][5];
    float* ob = out + (size_t)bb * CDIM * HW + hw0;
    #pragma unroll
    for (int i = 0; i < 16; i++) {
        const int c = wid * 16 + i;
        const float zc = zt[lane][c];
        const float ec = et[lane][c];
        const float q_ch = ec * rdnt;
        const float w_ch = (zc * rdns + q_ch) * rdnw;
        const float rot = zc - 2.0f * sw * w_ch + 2.0f * su * q_ch;
        ob[(size_t)c * HW + lane] = rot * scale;
    }
}

extern "C" void kernel_launch(void* const* d_in, const int* in_sizes, int n_in,
                              void* d_out, int out_size) {
    const float* z  = (const float*)d_in[0];   // (8,256,32,32)
    const float* cb = (const float*)d_in[1];   // (16384,256)
    const float* W  = (const float*)d_in[2];   // (256,256)
    float* out = (float*)d_out;

    cudaFuncSetAttribute(dist_kernel,
                         cudaFuncAttributeMaxDynamicSharedMemorySize, SMEM_DYN_D);
    cudaFuncSetAttribute(rotate_kernel,
                         cudaFuncAttributeMaxDynamicSharedMemorySize, SMEM_ROT);

    zsplit_kernel<<<dim3(4, NTOK / 64), 256>>>(z, out, out_size);
    emb_kernel<<<dim3(4, NE / 64), 256>>>(cb, W);
    dist_kernel<<<DGRID, DTHREADS, SMEM_DYN_D>>>(out);
    rotate_kernel<<<NTOK / 32, RTHREADS, SMEM_ROT>>>(z, out, out_size);
}